// round 17
// baseline (speedup 1.0000x reference)
#include <cuda_runtime.h>
#include <math.h>

#define BSZ 32
#define SEQ 512
#define IDIM 512
#define HDIM 512
#define G4H 2048

#define OUT_HT_ELEMS (BSZ*SEQ*2*HDIM)              // 16777216
#define OUT_HN_OFF   OUT_HT_ELEMS
#define OUT_CN_OFF   (OUT_HT_ELEMS + 2*BSZ*HDIM)   // 16809984
#define OUT_TOTAL    (OUT_CN_OFF + 2*BSZ*HDIM)     // 16842752

// Scratch (allocation-free rule: __device__ globals)
__device__ float    g_G[2][SEQ][BSZ][G4H];   // precomputed x@Wih^T + bias, 256MB
__device__ float    g_h[2][2][BSZ][HDIM];    // [buf][dir][b][k] double-buffered h
__device__ unsigned g_flag[2][2][64];        // [dir][half][cta] monotonic step flags

__device__ __forceinline__ unsigned ld_acq(const unsigned* p) {
    unsigned v;
    asm volatile("ld.acquire.gpu.global.u32 %0, [%1];" : "=r"(v) : "l"(p));
    return v;
}
__device__ __forceinline__ void st_rel(unsigned* p, unsigned v) {
    asm volatile("st.release.gpu.global.u32 [%0], %1;" :: "l"(p), "r"(v));
}
__device__ __forceinline__ void half_bar(int id) {
    asm volatile("bar.sync %0, 256;" :: "r"(id));
}
__device__ __forceinline__ void fma2(unsigned long long& acc,
                                     unsigned long long a, unsigned long long b) {
    asm("fma.rn.f32x2 %0, %1, %2, %0;" : "+l"(acc) : "l"(a), "l"(b));
}
__device__ __forceinline__ float red2(unsigned long long v) {
    float lo, hi;
    asm("mov.b64 {%0, %1}, %2;" : "=f"(lo), "=f"(hi) : "l"(v));
    return lo + hi;
}
__device__ __forceinline__ unsigned long long dup2(float x) {
    unsigned long long r;
    asm("mov.b64 %0, {%1, %1};" : "=l"(r) : "f"(x));
    return r;
}
__device__ __forceinline__ float2 upk2(unsigned long long v) {
    float2 r;
    asm("mov.b64 {%0, %1}, %2;" : "=f"(r.x), "=f"(r.y) : "l"(v));
    return r;
}
__device__ __forceinline__ float sigm(float x) {
    return 1.0f / (1.0f + __expf(-x));
}
__device__ __forceinline__ float tanh_fast(float x) {
    float xc = fminf(fmaxf(x, -10.0f), 10.0f);   // tanh(±10)=±1 in fp32; no overflow
    float e = __expf(2.0f * xc);
    return (e - 1.0f) / (e + 1.0f);
}

// ---------------------------------------------------------------------------
// Kernel 1: input-projection GEMM, v3: X stored in smem PRE-DUPLICATED as
// (x,x) u64 pairs -> inner loop is 3 LDS.128 + 8 FFMA2 per kk (no dup MOVs;
// was 2 LDS + 4 MOV + 8 FFMA2). 64x64 tile, TK=16, 256 threads.
// ---------------------------------------------------------------------------
__global__ void __launch_bounds__(256) ih_gemm_kernel(
    const float* __restrict__ X,
    const float* __restrict__ Wih_f, const float* __restrict__ bih_f, const float* __restrict__ bhh_f,
    const float* __restrict__ Wih_b, const float* __restrict__ bih_b, const float* __restrict__ bhh_b)
{
    __shared__ unsigned long long XsD[16][66];   // duplicated (x,x) pairs
    __shared__ float Ws[16][68];

    const int dir = blockIdx.z;
    const float* __restrict__ W   = dir ? Wih_b : Wih_f;
    const float* __restrict__ bih = dir ? bih_b : bih_f;
    const float* __restrict__ bhh = dir ? bhh_b : bhh_f;

    const int tid = threadIdx.x;
    const int tx = tid & 15;
    const int ty = tid >> 4;
    const int n0 = blockIdx.x * 64;
    const int m0 = blockIdx.y * 64;
    const int lrow = tid >> 2;
    const int lkq  = (tid & 3) * 4;

    unsigned long long acc2[4][2];
    #pragma unroll
    for (int i = 0; i < 4; i++) { acc2[i][0] = 0ull; acc2[i][1] = 0ull; }

    const float* Xp = X + (size_t)(m0 + lrow) * IDIM + lkq;
    const float* Wp = W + (size_t)(n0 + lrow) * IDIM + lkq;

    for (int k0 = 0; k0 < IDIM; k0 += 16) {
        float4 xv = *(const float4*)(Xp + k0);
        float4 wv = *(const float4*)(Wp + k0);
        XsD[lkq + 0][lrow] = dup2(xv.x);
        XsD[lkq + 1][lrow] = dup2(xv.y);
        XsD[lkq + 2][lrow] = dup2(xv.z);
        XsD[lkq + 3][lrow] = dup2(xv.w);
        Ws[lkq + 0][lrow] = wv.x; Ws[lkq + 1][lrow] = wv.y;
        Ws[lkq + 2][lrow] = wv.z; Ws[lkq + 3][lrow] = wv.w;
        __syncthreads();
        #pragma unroll
        for (int kk = 0; kk < 16; kk++) {
            const ulonglong2* ap = (const ulonglong2*)&XsD[kk][ty * 4];
            ulonglong2 a01 = ap[0];
            ulonglong2 a23 = ap[1];
            ulonglong2 bp = *(const ulonglong2*)&Ws[kk][tx * 4];
            fma2(acc2[0][0], a01.x, bp.x); fma2(acc2[0][1], a01.x, bp.y);
            fma2(acc2[1][0], a01.y, bp.x); fma2(acc2[1][1], a01.y, bp.y);
            fma2(acc2[2][0], a23.x, bp.x); fma2(acc2[2][1], a23.x, bp.y);
            fma2(acc2[3][0], a23.y, bp.x); fma2(acc2[3][1], a23.y, bp.y);
        }
        __syncthreads();
    }

    const int n = n0 + tx * 4;
    float4 bias4;
    bias4.x = bih[n + 0] + bhh[n + 0];
    bias4.y = bih[n + 1] + bhh[n + 1];
    bias4.z = bih[n + 2] + bhh[n + 2];
    bias4.w = bih[n + 3] + bhh[n + 3];

    float* Gout = &g_G[dir][0][0][0];
    #pragma unroll
    for (int mi = 0; mi < 4; mi++) {
        int m = m0 + ty * 4 + mi;
        int b = m >> 9;
        int t = m & 511;
        float2 u0 = upk2(acc2[mi][0]);
        float2 u1 = upk2(acc2[mi][1]);
        float4 o;
        o.x = u0.x + bias4.x;
        o.y = u0.y + bias4.y;
        o.z = u1.x + bias4.z;
        o.w = u1.y + bias4.w;
        *(float4*)(Gout + ((size_t)(t * BSZ + b) << 11) + n) = o;
    }
}

// ---------------------------------------------------------------------------
// Kernel 2: persistent recurrence, v10 — R15 structure + deferred reduction.
// In the bl loop, stop after fold16+fold8 (2 serial shfls instead of 5):
// every lane then holds a 4-lane partial of one row (slot = lane&7) and
// stores it to gsm2[row][slot][b] (write conflict-free: row stride 264=8,
// slot stride 33=1 mod 32). The gates phase sums the 8 slots + G (pipelined
// LDS, no serial shfl chain, no gsm RMW in the hot loop).
// 128 CTAs x 512 threads; concurrent batch halves, per-CTA flag barrier,
// fast-math gates, __ldcg/__stcg h traffic. hs is 64KB dynamic smem.
// ---------------------------------------------------------------------------
__global__ void __launch_bounds__(512) rec_kernel(
    const float* __restrict__ Whh_f, const float* __restrict__ Whh_b,
    float* __restrict__ out, int out_size)
{
    extern __shared__ float hs[];        // 64KB dynamic: both halves' h
    __shared__ float gsm2[32][8][33];    // [row][slot][b] partial sums
    __shared__ float gG[32][33];         // [row][b] input projection + bias
    __shared__ float csm[8][36];         // [jj][b] cell state (padded)
    __shared__ unsigned sbase[2];        // per-half flag snapshot

    const int tid  = threadIdx.x;
    const int cta  = blockIdx.x;
    const int dir  = cta >> 6;
    const int cd   = cta & 63;
    const int j0   = cd * 8;
    const int lane = tid & 31;
    const int warp = tid >> 5;           // 0..15
    const int rq   = warp & 7;           // rows 4rq..4rq+3
    const int bh   = warp >> 3;          // batch half (pipeline id)
    const int lt   = tid & 255;          // thread id within half
    const int barid = 1 + bh;
    const int q    = (lane >> 1) & 3;
    const int kbase = lane * 16;

    const float* __restrict__ Whh = dir ? Whh_b : Whh_f;

    int off[4];
    #pragma unroll
    for (int j = 0; j < 4; j++) off[j] = (j + q) & 3;

    // snapshot own flag BEFORE any store (all flags equal between replays)
    if (tid == 0) {
        sbase[0] = *(volatile unsigned*)&g_flag[dir][0][cd];
        sbase[1] = *(volatile unsigned*)&g_flag[dir][1][cd];
    }

    // Load 4 rows x 16 k of Whh into packed u64 registers, swizzled k order
    unsigned long long w2[4][8];
    #pragma unroll
    for (int r = 0; r < 4; r++) {
        int r_local = 4 * rq + r;
        int gate = r_local >> 3;
        int jj   = r_local & 7;
        const ulonglong2* wrow =
            (const ulonglong2*)(Whh + (size_t)(gate * HDIM + j0 + jj) * HDIM + kbase);
        #pragma unroll
        for (int j = 0; j < 4; j++) {
            ulonglong2 wv = wrow[off[j]];
            w2[r][2 * j]     = wv.x;
            w2[r][2 * j + 1] = wv.y;
        }
    }

    // zero this direction's initial h (buf 0) + cell state
    if (tid < 256) __stcg(&(&g_h[0][dir][0][0])[cd * 256 + tid], 0.0f);
    for (int i = tid; i < 8 * 36; i += 512) ((float*)csm)[i] = 0.0f;

    // preload step-0 input projection for this half into gG
    if (lt < 128) {
        const int t0 = dir ? (SEQ - 1) : 0;
        int bb = bh * 16 + (lt >> 3);
        int r0 = (lt & 7) * 4;
        int gg = r0 >> 3;
        int j4 = r0 & 7;
        float4 gv = *(const float4*)&g_G[dir][t0][bb][gg * HDIM + j0 + j4];
        gG[r0 + 0][bb] = gv.x; gG[r0 + 1][bb] = gv.y;
        gG[r0 + 2][bb] = gv.z; gG[r0 + 3][bb] = gv.w;
    }

    __syncthreads();   // orders zero-init, csm, gG, sbase for everyone
    const unsigned base0 = sbase[0];
    const unsigned base1 = sbase[1];
    const unsigned base  = bh ? base1 : base0;

    // init arrival: publish zeroed h(0) for this half (own flag only)
    if (lt == 0) st_rel(&g_flag[dir][bh][cd], base + 1u);

    const bool write_tail = (out_size >= OUT_TOTAL);
    // lane's row after fold16+fold8: 4rq + 2*bit4 + bit3
    const int  r_red = 4 * rq + ((lane >> 4) & 1) * 2 + ((lane >> 3) & 1);
    const int  slot  = lane & 7;
    const bool hi16 = (lane & 16) != 0;
    const bool hi8  = (lane & 8)  != 0;
    const bool pollwarp = (warp == bh * 8);   // warp 0 / warp 8

    for (int s = 0; s < SEQ; s++) {
        const int cur = s & 1, nxt = cur ^ 1;
        const int t = dir ? (SEQ - 1 - s) : s;

        // ---- wait: all 64 CTAs published h(s) for this half ----
        if (pollwarp) {
            const unsigned* fl = &g_flag[dir][bh][0];
            const unsigned target = base + 1u + (unsigned)s;
            for (;;) {
                bool ok = ((int)(ld_acq(fl + lane) - target) >= 0) &&
                          ((int)(ld_acq(fl + lane + 32) - target) >= 0);
                if (__all_sync(0xffffffffu, ok)) break;
            }
            if (bh == 1) {
                // anti-phase skew: half A must have FINISHED step min(s+1,511)
                const int k = (s + 1 < SEQ) ? (s + 1) : (SEQ - 1);
                const unsigned ta = base0 + 2u + (unsigned)k;
                const unsigned* fa = &g_flag[dir][0][0];
                for (;;) {
                    bool ok = ((int)(ld_acq(fa + lane) - ta) >= 0) &&
                              ((int)(ld_acq(fa + lane + 32) - ta) >= 0);
                    if (__all_sync(0xffffffffu, ok)) break;
                }
            }
        }
        half_bar(barid);

        // ---- stage this half's h[16][512] into smem (L1-bypassing loads) ----
        {
            const float4* src = (const float4*)&g_h[cur][dir][bh * 16][0];
            float4* dst = (float4*)(hs + bh * 16 * HDIM);
            #pragma unroll
            for (int i = 0; i < 8; i++)
                dst[lt + 256 * i] = __ldcg(&src[lt + 256 * i]);
        }
        half_bar(barid);

        // ---- recurrent GEMM for this half's 16 batch rows ----
        const float* hrow = hs + kbase + bh * (16 * HDIM);
        #pragma unroll 2
        for (int bl = 0; bl < 16; bl++) {
            const int b = bh * 16 + bl;
            const ulonglong2* hp = (const ulonglong2*)(hrow + bl * HDIM);
            unsigned long long ha[8];
            #pragma unroll
            for (int j = 0; j < 4; j++) {
                ulonglong2 hv = hp[off[j]];       // swizzled: conflict-free
                ha[2 * j]     = hv.x;
                ha[2 * j + 1] = hv.y;
            }
            unsigned long long a0 = 0, a1 = 0, a2 = 0, a3 = 0;
            #pragma unroll
            for (int j = 0; j < 8; j++) {
                fma2(a0, ha[j], w2[0][j]);
                fma2(a1, ha[j], w2[1][j]);
                fma2(a2, ha[j], w2[2][j]);
                fma2(a3, ha[j], w2[3][j]);
            }
            float s0 = red2(a0), s1 = red2(a1), s2 = red2(a2), s3 = red2(a3);
            // fold16 + fold8 only (2 serial shfls); store 8 partials per row
            float t0 = hi16 ? s0 : s2;
            float p0 = (hi16 ? s2 : s0) + __shfl_xor_sync(0xffffffffu, t0, 16);
            float t1 = hi16 ? s1 : s3;
            float p1 = (hi16 ? s3 : s1) + __shfl_xor_sync(0xffffffffu, t1, 16);
            float t2 = hi8 ? p0 : p1;
            float v  = (hi8 ? p1 : p0) + __shfl_xor_sync(0xffffffffu, t2, 8);
            gsm2[r_red][slot][b] = v;             // all 32 lanes, distinct banks
        }
        half_bar(barid);

        // ---- gates for this half: thread -> (ej, b); sum 8 slots + G ----
        if (lt < 128) {
            const int ej = lt & 7;
            const int b  = bh * 16 + (lt >> 3);
            float ga[4];
            #pragma unroll
            for (int g = 0; g < 4; g++) {
                const int row = g * 8 + ej;
                float v = gG[row][b];
                float u0 = gsm2[row][0][b] + gsm2[row][1][b];
                float u1 = gsm2[row][2][b] + gsm2[row][3][b];
                float u2 = gsm2[row][4][b] + gsm2[row][5][b];
                float u3 = gsm2[row][6][b] + gsm2[row][7][b];
                ga[g] = v + ((u0 + u1) + (u2 + u3));
            }
            float c = csm[ej][b];
            c = sigm(ga[1]) * c + sigm(ga[0]) * tanh_fast(ga[2]);
            float h = sigm(ga[3]) * tanh_fast(c);
            csm[ej][b] = c;
            __stcg(&g_h[nxt][dir][b][j0 + ej], h);
            out[(size_t)(b * SEQ + t) * (2 * HDIM) + dir * HDIM + j0 + ej] = h;
            if (s == SEQ - 1 && write_tail) {
                out[OUT_HN_OFF + dir * (BSZ * HDIM) + b * HDIM + j0 + ej] = h;
                out[OUT_CN_OFF + dir * (BSZ * HDIM) + b * HDIM + j0 + ej] = c;
            }
        }
        half_bar(barid);   // h stores + gsm2/gG reads done for this half

        // ---- arrive: publish h(s+1) — own flag, no atomics ----
        if (lt == 0) st_rel(&g_flag[dir][bh][cd], base + 2u + (unsigned)s);

        // ---- preload next step's G for this half ----
        if (s + 1 < SEQ && lt < 128) {
            int tn = dir ? (SEQ - 2 - s) : (s + 1);
            int bb = bh * 16 + (lt >> 3);
            int r0 = (lt & 7) * 4;
            int gg = r0 >> 3;
            int j4 = r0 & 7;
            float4 gv = *(const float4*)&g_G[dir][tn][bb][gg * HDIM + j0 + j4];
            gG[r0 + 0][bb] = gv.x; gG[r0 + 1][bb] = gv.y;
            gG[r0 + 2][bb] = gv.z; gG[r0 + 3][bb] = gv.w;
        }
    }
}

extern "C" void kernel_launch(void* const* d_in, const int* in_sizes, int n_in,
                              void* d_out, int out_size) {
    const float* X     = (const float*)d_in[0];
    const float* Wih_f = (const float*)d_in[1];
    const float* Whh_f = (const float*)d_in[2];
    const float* bih_f = (const float*)d_in[3];
    const float* bhh_f = (const float*)d_in[4];
    const float* Wih_b = (const float*)d_in[5];
    const float* Whh_b = (const float*)d_in[6];
    const float* bih_b = (const float*)d_in[7];
    const float* bhh_b = (const float*)d_in[8];
    float* out = (float*)d_out;

    cudaFuncSetAttribute(rec_kernel, cudaFuncAttributeMaxDynamicSharedMemorySize,
                         32 * HDIM * (int)sizeof(float));

    dim3 g1(G4H / 64, (BSZ * SEQ) / 64, 2);
    ih_gemm_kernel<<<g1, 256>>>(X, Wih_f, bih_f, bhh_f, Wih_b, bih_b, bhh_b);
    rec_kernel<<<128, 512, 32 * HDIM * sizeof(float)>>>(Whh_f, Whh_b, out, out_size);
}